// round 2
// baseline (speedup 1.0000x reference)
#include <cuda_runtime.h>
#include <cstdint>

#define HG_L 16
#define HG_T (1u << 19)
#define HG_TMASK (HG_T - 1u)
#define WIDTH 64

#define P1 2654435761u
#define P2 805459861u
#define P3 3674653429u

// floor(16 * 1.5^l) for l = 0..15
__constant__ float c_res[HG_L] = {
    16.f, 24.f, 36.f, 54.f, 81.f, 121.f, 182.f, 273.f,
    410.f, 615.f, 922.f, 1383.f, 2075.f, 3113.f, 4670.f, 7006.f
};

// Padded smem layouts: two 32-wide halves per row, half 1 at +36 floats so the
// two sub-lanes of a pair hit disjoint banks (no 2-way conflict).
#define ROWP 72
#define HOFF 36

// Accumulate 4 consecutive W1 rows (2 levels x 2 features) into this lane's
// 32-wide half of h1. w points at the row block (padded layout), sub selects half.
__device__ __forceinline__ void acc4(const float* __restrict__ w, int sub,
                                     float a0, float a1, float b0, float b1,
                                     float* __restrict__ h1) {
    const float* p = w + sub * HOFF;
#pragma unroll
    for (int j = 0; j < 32; j += 4) {
        float4 r0 = *(const float4*)(p + j);
        float4 r1 = *(const float4*)(p + ROWP + j);
        float4 r2 = *(const float4*)(p + 2 * ROWP + j);
        float4 r3 = *(const float4*)(p + 3 * ROWP + j);
        h1[j + 0] = fmaf(a0, r0.x, fmaf(a1, r1.x, fmaf(b0, r2.x, fmaf(b1, r3.x, h1[j + 0]))));
        h1[j + 1] = fmaf(a0, r0.y, fmaf(a1, r1.y, fmaf(b0, r2.y, fmaf(b1, r3.y, h1[j + 1]))));
        h1[j + 2] = fmaf(a0, r0.z, fmaf(a1, r1.z, fmaf(b0, r2.z, fmaf(b1, r3.z, h1[j + 2]))));
        h1[j + 3] = fmaf(a0, r0.w, fmaf(a1, r1.w, fmaf(b0, r2.w, fmaf(b1, r3.w, h1[j + 3]))));
    }
}

// 3D encode, pair-split: lane handles level 2s+sub of its point; features
// exchanged with the partner lane via shfl.xor(16).
__device__ __forceinline__ void encode3(float x0, float x1, float x2,
                                        const float* __restrict__ tab,
                                        const float* __restrict__ W1s,
                                        int kbase, int sub,
                                        float* __restrict__ h1) {
#pragma unroll 1
    for (int s = 0; s < 8; s++) {
        const int lo = 2 * s + sub;
        float r = c_res[lo];
        float px = x0 * r, py = x1 * r, pz = x2 * r;
        float fx = floorf(px), fy = floorf(py), fz = floorf(pz);
        float wx = px - fx, wy = py - fy, wz = pz - fz;

        uint32_t ax[2], ay[2], az[2];
        ax[0] = (uint32_t)fx;        ax[1] = ax[0] + 1u;
        ay[0] = (uint32_t)fy * P1;   ay[1] = ay[0] + P1;
        az[0] = (uint32_t)fz * P2;   az[1] = az[0] + P2;
        float vx[2] = {1.f - wx, wx};
        float vy[2] = {1.f - wy, wy};
        float vz[2] = {1.f - wz, wz};

        const float2* base = (const float2*)tab + (size_t)lo * HG_T;
        float f0 = 0.f, f1 = 0.f;
#pragma unroll
        for (int c = 0; c < 8; c++) {
            const int bx = (c >> 2) & 1, by = (c >> 1) & 1, bz = c & 1;
            uint32_t id = (ax[bx] ^ ay[by] ^ az[bz]) & HG_TMASK;
            float2 f = __ldg(base + id);
            float wt = vx[bx] * vy[by] * vz[bz];
            f0 = fmaf(wt, f.x, f0);
            f1 = fmaf(wt, f.y, f1);
        }
        float g0 = __shfl_xor_sync(0xffffffffu, f0, 16);
        float g1 = __shfl_xor_sync(0xffffffffu, f1, 16);
        // level 2s features / level 2s+1 features, in level order
        float a0 = sub ? g0 : f0, a1 = sub ? g1 : f1;
        float b0 = sub ? f0 : g0, b1 = sub ? f1 : g1;
        acc4(W1s + (size_t)(kbase + 4 * s) * ROWP, sub, a0, a1, b0, b1, h1);
    }
}

// 4D encode, pair-split.
__device__ __forceinline__ void encode4(float x0, float x1, float x2, float x3,
                                        const float* __restrict__ tab,
                                        const float* __restrict__ W1s,
                                        int kbase, int sub,
                                        float* __restrict__ h1) {
#pragma unroll 1
    for (int s = 0; s < 8; s++) {
        const int lo = 2 * s + sub;
        float r = c_res[lo];
        float px = x0 * r, py = x1 * r, pz = x2 * r, pw = x3 * r;
        float fx = floorf(px), fy = floorf(py), fz = floorf(pz), fw = floorf(pw);
        float wx = px - fx, wy = py - fy, wz = pz - fz, ww = pw - fw;

        uint32_t ax[2], ay[2], az[2], aw[2];
        ax[0] = (uint32_t)fx;        ax[1] = ax[0] + 1u;
        ay[0] = (uint32_t)fy * P1;   ay[1] = ay[0] + P1;
        az[0] = (uint32_t)fz * P2;   az[1] = az[0] + P2;
        aw[0] = (uint32_t)fw * P3;   aw[1] = aw[0] + P3;
        float vx[2] = {1.f - wx, wx};
        float vy[2] = {1.f - wy, wy};
        float vz[2] = {1.f - wz, wz};
        float vw[2] = {1.f - ww, ww};

        const float2* base = (const float2*)tab + (size_t)lo * HG_T;
        float f0 = 0.f, f1 = 0.f;
#pragma unroll
        for (int c = 0; c < 16; c++) {
            const int bx = (c >> 3) & 1, by = (c >> 2) & 1, bz = (c >> 1) & 1, bw = c & 1;
            uint32_t id = (ax[bx] ^ ay[by] ^ az[bz] ^ aw[bw]) & HG_TMASK;
            float2 f = __ldg(base + id);
            float wt = (vx[bx] * vy[by]) * (vz[bz] * vw[bw]);
            f0 = fmaf(wt, f.x, f0);
            f1 = fmaf(wt, f.y, f1);
        }
        float g0 = __shfl_xor_sync(0xffffffffu, f0, 16);
        float g1 = __shfl_xor_sync(0xffffffffu, f1, 16);
        float a0 = sub ? g0 : f0, a1 = sub ? g1 : f1;
        float b0 = sub ? f0 : g0, b1 = sub ? f1 : g1;
        acc4(W1s + (size_t)(kbase + 4 * s) * ROWP, sub, a0, a1, b0, b1, h1);
    }
}

__global__ __launch_bounds__(256, 3)
void hashgrid_mlp_kernel(const float* __restrict__ fc,
                         const float* __restrict__ fn,
                         const float* __restrict__ pe,
                         const float* __restrict__ pos_tab,
                         const float* __restrict__ nrm_tab,
                         const float* __restrict__ pose_tab,
                         const float* __restrict__ W1,
                         const float* __restrict__ W2,
                         const float* __restrict__ W3,
                         float* __restrict__ out, int n) {
    __shared__ float W1s[96 * ROWP];    // [96][2 halves of 32, skewed] 27 KB
    __shared__ float W2Ts[64 * ROWP];   // transposed W2, same half-skew  18 KB
    __shared__ float W3s[64 * 9];       //                                2.25 KB

    const int tid = threadIdx.x;
    for (int i = tid; i < 96 * 64; i += 256) {
        int row = i >> 6, col = i & 63;
        W1s[row * ROWP + (col >> 5) * HOFF + (col & 31)] = W1[i];
    }
    for (int i = tid; i < 64 * 64; i += 256) {
        int k = i >> 6, j = i & 63;           // W2[k][j]
        W2Ts[j * ROWP + (k >> 5) * HOFF + (k & 31)] = W2[i];
    }
    for (int i = tid; i < 64 * 9; i += 256) W3s[i] = W3[i];
    __syncthreads();

    const int warp = tid >> 5;
    const int lane = tid & 31;
    const int sub = lane >> 4;          // which half of the pair
    const int pt = lane & 15;           // point slot within warp
    const int pidx = blockIdx.x * 128 + warp * 16 + pt;
    const int pc = (pidx < n) ? pidx : (n - 1);   // clamped: all lanes stay active for shfl

    float h1[32];
#pragma unroll
    for (int j = 0; j < 32; j++) h1[j] = 0.f;

    {
        float x0 = __ldg(fc + (size_t)pc * 3 + 0);
        float x1 = __ldg(fc + (size_t)pc * 3 + 1);
        float x2 = __ldg(fc + (size_t)pc * 3 + 2);
        encode3(x0, x1, x2, pos_tab, W1s, 0, sub, h1);
    }
    {
        float x0 = __ldg(fn + (size_t)pc * 3 + 0);
        float x1 = __ldg(fn + (size_t)pc * 3 + 1);
        float x2 = __ldg(fn + (size_t)pc * 3 + 2);
        encode3(x0, x1, x2, nrm_tab, W1s, 32, sub, h1);
    }
    {
        float x0 = __ldg(pe + (size_t)pc * 4 + 0);
        float x1 = __ldg(pe + (size_t)pc * 4 + 1);
        float x2 = __ldg(pe + (size_t)pc * 4 + 2);
        float x3 = __ldg(pe + (size_t)pc * 4 + 3);
        encode4(x0, x1, x2, x3, pose_tab, W1s, 64, sub, h1);
    }

    // relu(layer 1) — this lane's 32-wide half
#pragma unroll
    for (int k = 0; k < 32; k++) h1[k] = fmaxf(h1[k], 0.f);

    // layers 2 + 3, pair-split: partial dot over own half, shuffle-combine.
    float acc[9];
#pragma unroll
    for (int o = 0; o < 9; o++) acc[o] = 0.f;

#pragma unroll 2
    for (int j = 0; j < WIDTH; j++) {
        const float* wr = W2Ts + (size_t)j * ROWP + sub * HOFF;
        float s0 = 0.f, s1 = 0.f, s2 = 0.f, s3 = 0.f;
#pragma unroll
        for (int k = 0; k < 32; k += 4) {
            float4 a = *(const float4*)(wr + k);
            s0 = fmaf(h1[k + 0], a.x, s0);
            s1 = fmaf(h1[k + 1], a.y, s1);
            s2 = fmaf(h1[k + 2], a.z, s2);
            s3 = fmaf(h1[k + 3], a.w, s3);
        }
        float part = (s0 + s1) + (s2 + s3);
        float sfull = part + __shfl_xor_sync(0xffffffffu, part, 16);
        sfull = fmaxf(sfull, 0.f);
        const float* w3 = W3s + j * 9;
#pragma unroll
        for (int o = 0; o < 9; o++) acc[o] = fmaf(sfull, w3[o], acc[o]);
    }

    if (pidx < n) {
        float* op = out + (size_t)pidx * 9;
        if (sub == 0) {
            op[0] = acc[0]; op[1] = acc[1]; op[2] = acc[2]; op[3] = acc[3]; op[4] = acc[4];
        } else {
            op[5] = acc[5]; op[6] = acc[6]; op[7] = acc[7]; op[8] = acc[8];
        }
    }
}

extern "C" void kernel_launch(void* const* d_in, const int* in_sizes, int n_in,
                              void* d_out, int out_size) {
    const float* fc = (const float*)d_in[0];
    const float* fn = (const float*)d_in[1];
    const float* pe = (const float*)d_in[2];
    const float* pt = (const float*)d_in[3];
    const float* nt = (const float*)d_in[4];
    const float* qt = (const float*)d_in[5];
    const float* W1 = (const float*)d_in[6];
    const float* W2 = (const float*)d_in[7];
    const float* W3 = (const float*)d_in[8];
    float* out = (float*)d_out;

    const int n = in_sizes[0] / 3;
    const int blocks = (n + 127) / 128;   // 128 points per 256-thread block
    hashgrid_mlp_kernel<<<blocks, 256>>>(fc, fn, pe, pt, nt, qt, W1, W2, W3, out, n);
}

// round 3
// speedup vs baseline: 1.4965x; 1.4965x over previous
#include <cuda_runtime.h>
#include <cstdint>

#define HG_L 16
#define HG_T (1u << 19)
#define HG_TMASK (HG_T - 1u)
#define WIDTH 64

#define P1 2654435761u
#define P2 805459861u
#define P3 3674653429u

typedef unsigned long long u64;

// floor(16 * 1.5^l) for l = 0..15
__constant__ float c_res[HG_L] = {
    16.f, 24.f, 36.f, 54.f, 81.f, 121.f, 182.f, 273.f,
    410.f, 615.f, 922.f, 1383.f, 2075.f, 3113.f, 4670.f, 7006.f
};

// packed f32x2 fma: d = a*b + c on both halves (Blackwell FFMA2)
__device__ __forceinline__ u64 ffma2(u64 a, u64 b, u64 c) {
    u64 d;
    asm("fma.rn.f32x2 %0, %1, %2, %3;" : "=l"(d) : "l"(a), "l"(b), "l"(c));
    return d;
}
__device__ __forceinline__ u64 dup2(float x) {
    u64 d;
    asm("mov.b64 %0, {%1, %1};" : "=l"(d) : "f"(x));
    return d;
}

// Accumulate one level's (f0, f1) into h1 (32 packed f32x2 regs) using W1
// rows (row, row+1). Smem reads are warp-uniform broadcast LDS.128.
__device__ __forceinline__ void acc_l1(const float* __restrict__ W1s, int row,
                                       float f0, float f1, u64* __restrict__ hp) {
    u64 F0 = dup2(f0), F1 = dup2(f1);
    const ulonglong2* w0 = (const ulonglong2*)(W1s + row * WIDTH);
    const ulonglong2* w1 = (const ulonglong2*)(W1s + (row + 1) * WIDTH);
#pragma unroll
    for (int j = 0; j < 16; j++) {
        ulonglong2 a = w0[j];
        ulonglong2 b = w1[j];
        hp[2 * j + 0] = ffma2(F0, a.x, ffma2(F1, b.x, hp[2 * j + 0]));
        hp[2 * j + 1] = ffma2(F0, a.y, ffma2(F1, b.y, hp[2 * j + 1]));
    }
}

// 3D encode fused with layer-1. x-corner pairs merge to one float4 gather
// when floor(x*r) is even (PRIMES[0]==1 => ids differ only in bit 0).
__device__ __forceinline__ void encode3(float x0, float x1, float x2,
                                        const float* __restrict__ tab,
                                        const float* __restrict__ W1s,
                                        int kbase, u64* __restrict__ hp) {
#pragma unroll 1
    for (int l = 0; l < HG_L; l++) {
        float r = c_res[l];
        float px = x0 * r, py = x1 * r, pz = x2 * r;
        float fx = floorf(px), fy = floorf(py), fz = floorf(pz);
        float wx = px - fx, wy = py - fy, wz = pz - fz;

        uint32_t ax0 = (uint32_t)fx;
        uint32_t ey[2], ez[2];
        ey[0] = (uint32_t)fy * P1;  ey[1] = ey[0] + P1;
        ez[0] = (uint32_t)fz * P2;  ez[1] = ez[0] + P2;
        float vx0 = 1.f - wx, vx1 = wx;
        float vy[2] = {1.f - wy, wy};
        float vz[2] = {1.f - wz, wz};

        const float2* base = (const float2*)tab + (size_t)l * HG_T;
        float f0 = 0.f, f1 = 0.f;

        if ((ax0 & 1u) == 0u) {
            const float4* b4 = (const float4*)base;
#pragma unroll
            for (int c = 0; c < 4; c++) {
                const int by = c >> 1, bz = c & 1;
                uint32_t id0 = (ax0 ^ ey[by] ^ ez[bz]) & HG_TMASK;
                float4 q = __ldg(b4 + (id0 >> 1));
                bool h = (id0 & 1u) != 0u;
                float wl = h ? vx1 : vx0;   // weight on entries q.xy
                float wh = h ? vx0 : vx1;   // weight on entries q.zw
                float wt = vy[by] * vz[bz];
                f0 = fmaf(wt, fmaf(wl, q.x, wh * q.z), f0);
                f1 = fmaf(wt, fmaf(wl, q.y, wh * q.w), f1);
            }
        } else {
            uint32_t ax1 = ax0 + 1u;
#pragma unroll
            for (int c = 0; c < 4; c++) {
                const int by = c >> 1, bz = c & 1;
                uint32_t e = ey[by] ^ ez[bz];
                float2 u = __ldg(base + ((ax0 ^ e) & HG_TMASK));
                float2 v = __ldg(base + ((ax1 ^ e) & HG_TMASK));
                float wt = vy[by] * vz[bz];
                f0 = fmaf(wt, fmaf(vx0, u.x, vx1 * v.x), f0);
                f1 = fmaf(wt, fmaf(vx0, u.y, vx1 * v.y), f1);
            }
        }
        acc_l1(W1s, kbase + 2 * l, f0, f1, hp);
    }
}

// 4D encode, same merge on the x-dimension corner pairs.
__device__ __forceinline__ void encode4(float x0, float x1, float x2, float x3,
                                        const float* __restrict__ tab,
                                        const float* __restrict__ W1s,
                                        int kbase, u64* __restrict__ hp) {
#pragma unroll 1
    for (int l = 0; l < HG_L; l++) {
        float r = c_res[l];
        float px = x0 * r, py = x1 * r, pz = x2 * r, pw = x3 * r;
        float fx = floorf(px), fy = floorf(py), fz = floorf(pz), fw = floorf(pw);
        float wx = px - fx, wy = py - fy, wz = pz - fz, ww = pw - fw;

        uint32_t ax0 = (uint32_t)fx;
        uint32_t ey[2], ez[2], ew[2];
        ey[0] = (uint32_t)fy * P1;  ey[1] = ey[0] + P1;
        ez[0] = (uint32_t)fz * P2;  ez[1] = ez[0] + P2;
        ew[0] = (uint32_t)fw * P3;  ew[1] = ew[0] + P3;
        float vx0 = 1.f - wx, vx1 = wx;
        float vy[2] = {1.f - wy, wy};
        float vz[2] = {1.f - wz, wz};
        float vw[2] = {1.f - ww, ww};

        const float2* base = (const float2*)tab + (size_t)l * HG_T;
        float f0 = 0.f, f1 = 0.f;

        if ((ax0 & 1u) == 0u) {
            const float4* b4 = (const float4*)base;
#pragma unroll
            for (int c = 0; c < 8; c++) {
                const int by = (c >> 2) & 1, bz = (c >> 1) & 1, bw = c & 1;
                uint32_t id0 = (ax0 ^ ey[by] ^ ez[bz] ^ ew[bw]) & HG_TMASK;
                float4 q = __ldg(b4 + (id0 >> 1));
                bool h = (id0 & 1u) != 0u;
                float wl = h ? vx1 : vx0;
                float wh = h ? vx0 : vx1;
                float wt = vy[by] * (vz[bz] * vw[bw]);
                f0 = fmaf(wt, fmaf(wl, q.x, wh * q.z), f0);
                f1 = fmaf(wt, fmaf(wl, q.y, wh * q.w), f1);
            }
        } else {
            uint32_t ax1 = ax0 + 1u;
#pragma unroll
            for (int c = 0; c < 8; c++) {
                const int by = (c >> 2) & 1, bz = (c >> 1) & 1, bw = c & 1;
                uint32_t e = ey[by] ^ ez[bz] ^ ew[bw];
                float2 u = __ldg(base + ((ax0 ^ e) & HG_TMASK));
                float2 v = __ldg(base + ((ax1 ^ e) & HG_TMASK));
                float wt = vy[by] * (vz[bz] * vw[bw]);
                f0 = fmaf(wt, fmaf(vx0, u.x, vx1 * v.x), f0);
                f1 = fmaf(wt, fmaf(vx0, u.y, vx1 * v.y), f1);
            }
        }
        acc_l1(W1s, kbase + 2 * l, f0, f1, hp);
    }
}

__global__ __launch_bounds__(256, 2)
void hashgrid_mlp_kernel(const float* __restrict__ fc,
                         const float* __restrict__ fn,
                         const float* __restrict__ pe,
                         const float* __restrict__ pos_tab,
                         const float* __restrict__ nrm_tab,
                         const float* __restrict__ pose_tab,
                         const float* __restrict__ W1,
                         const float* __restrict__ W2,
                         const float* __restrict__ W3,
                         float* __restrict__ out, int n) {
    __shared__ float W1s[96 * WIDTH];       // 24 KB   [96][64]
    __shared__ float W2Ts[WIDTH * WIDTH];   // 16 KB   W2Ts[j][k] = W2[k][j]
    __shared__ float W3s[WIDTH * 9];        // 2.25 KB [64][9]

    const int tid = threadIdx.x;
    for (int i = tid; i < 96 * WIDTH; i += 256) W1s[i] = W1[i];
    for (int i = tid; i < WIDTH * WIDTH; i += 256) {
        int k = i >> 6, j = i & 63;
        W2Ts[j * WIDTH + k] = W2[i];
    }
    for (int i = tid; i < WIDTH * 9; i += 256) W3s[i] = W3[i];
    __syncthreads();

    const int idx = blockIdx.x * 256 + tid;
    if (idx >= n) return;

    u64 hp[32];                   // h1[64] as 32 packed f32x2
#pragma unroll
    for (int j = 0; j < 32; j++) hp[j] = 0ull;

    {
        float x0 = __ldg(fc + (size_t)idx * 3 + 0);
        float x1 = __ldg(fc + (size_t)idx * 3 + 1);
        float x2 = __ldg(fc + (size_t)idx * 3 + 2);
        encode3(x0, x1, x2, pos_tab, W1s, 0, hp);
    }
    {
        float x0 = __ldg(fn + (size_t)idx * 3 + 0);
        float x1 = __ldg(fn + (size_t)idx * 3 + 1);
        float x2 = __ldg(fn + (size_t)idx * 3 + 2);
        encode3(x0, x1, x2, nrm_tab, W1s, 32, hp);
    }
    {
        float x0 = __ldg(pe + (size_t)idx * 4 + 0);
        float x1 = __ldg(pe + (size_t)idx * 4 + 1);
        float x2 = __ldg(pe + (size_t)idx * 4 + 2);
        float x3 = __ldg(pe + (size_t)idx * 4 + 3);
        encode4(x0, x1, x2, x3, pose_tab, W1s, 64, hp);
    }

    // unpack + relu(layer 1)
    float h1[WIDTH];
#pragma unroll
    for (int j = 0; j < 32; j++) {
        float lo, hi;
        asm("mov.b64 {%0, %1}, %2;" : "=f"(lo), "=f"(hi) : "l"(hp[j]));
        h1[2 * j + 0] = fmaxf(lo, 0.f);
        h1[2 * j + 1] = fmaxf(hi, 0.f);
    }

    // layers 2 + 3 streamed
    float acc[9];
#pragma unroll
    for (int o = 0; o < 9; o++) acc[o] = 0.f;

#pragma unroll 1
    for (int j = 0; j < WIDTH; j++) {
        const float* wr = W2Ts + j * WIDTH;
        float s0 = 0.f, s1 = 0.f, s2 = 0.f, s3 = 0.f;
#pragma unroll
        for (int k = 0; k < WIDTH; k += 4) {
            float4 a = *(const float4*)(wr + k);
            s0 = fmaf(h1[k + 0], a.x, s0);
            s1 = fmaf(h1[k + 1], a.y, s1);
            s2 = fmaf(h1[k + 2], a.z, s2);
            s3 = fmaf(h1[k + 3], a.w, s3);
        }
        float s = fmaxf((s0 + s1) + (s2 + s3), 0.f);
        const float* w3 = W3s + j * 9;
#pragma unroll
        for (int o = 0; o < 9; o++) acc[o] = fmaf(s, w3[o], acc[o]);
    }

    float* op = out + (size_t)idx * 9;
#pragma unroll
    for (int o = 0; o < 9; o++) op[o] = acc[o];
}

extern "C" void kernel_launch(void* const* d_in, const int* in_sizes, int n_in,
                              void* d_out, int out_size) {
    const float* fc = (const float*)d_in[0];
    const float* fn = (const float*)d_in[1];
    const float* pe = (const float*)d_in[2];
    const float* pt = (const float*)d_in[3];
    const float* nt = (const float*)d_in[4];
    const float* qt = (const float*)d_in[5];
    const float* W1 = (const float*)d_in[6];
    const float* W2 = (const float*)d_in[7];
    const float* W3 = (const float*)d_in[8];
    float* out = (float*)d_out;

    const int n = in_sizes[0] / 3;
    const int blocks = (n + 255) / 256;
    hashgrid_mlp_kernel<<<blocks, 256>>>(fc, fn, pe, pt, nt, qt, W1, W2, W3, out, n);
}